// round 3
// baseline (speedup 1.0000x reference)
#include <cuda_runtime.h>
#include <math_constants.h>

#define FH 64
#define FW 64
#define FC 128
#define NB 2
#define NROI 256
#define OH 7
#define OW 7
#define NBIN (OH * OW)          // 49
#define SCALE 0.0625f
#define C4 (FC / 4)             // 32 float4 per pixel

// NHWC scratch: [b][y][x][c], 4 MB (device global, no alloc)
__device__ float g_feat_t[NB * FH * FW * FC];

// ---------------------------------------------------------------------------
// Kernel 1: NCHW -> NHWC. One block per (b, y, channel-half): 256 blocks.
// ---------------------------------------------------------------------------
__global__ __launch_bounds__(256) void transpose_nchw_nhwc(const float* __restrict__ feat) {
    __shared__ float s[64][FW + 1];          // 64 x 65 floats = 16.6 KB
    int blk = blockIdx.x;                    // 0..255
    int choff = (blk & 1) * 64;              // channel half
    int row = blk >> 1;                      // 0..127 : b*64 + y
    int b = row >> 6;
    int y = row & 63;

    // feat[b][choff+c][y][x]
    const float* src = feat + (((size_t)b * FC + choff) * FH + y) * FW;
    #pragma unroll
    for (int it = 0; it < 16; ++it) {
        int idx = threadIdx.x + it * 256;    // 4096 elems
        int c = idx >> 6;
        int x = idx & 63;
        s[c][x] = src[(size_t)c * FH * FW + x];   // coalesced 256B reads
    }
    __syncthreads();

    // g_feat_t[b][y][x][choff + c]
    float* dst = g_feat_t + (size_t)row * FW * FC + choff;
    #pragma unroll
    for (int it = 0; it < 16; ++it) {
        int idx = threadIdx.x + it * 256;
        int x = idx >> 6;
        int c = idx & 63;
        dst[(size_t)x * FC + c] = s[c][x];   // coalesced 256B writes, bank-free
    }
}

// ---------------------------------------------------------------------------
// Kernel 2: one block (512 thr = 16 warps) per ROI.
// Warp handles bins {w, w+16, w+32, (48)}. Lane layout: p = lane>>4 (x-pixel
// offset 0/1), ch4 = lane&15 (float4 chunk within a 64-channel half).
// Each x-iteration issues 4 independent loads (2 ch-halves x 2 rows) covering
// a 2x2 pixel patch x 128 channels -> ~4x MLP vs round 2.
// ---------------------------------------------------------------------------
__global__ __launch_bounds__(512) void roipool_kernel(const float* __restrict__ rois,
                                                      float* __restrict__ out) {
    __shared__ float s_out[FC * NBIN];       // [c][bin] flat

    int r    = blockIdx.x;
    int wid  = threadIdx.x >> 5;
    int lane = threadIdx.x & 31;
    int p    = lane >> 4;                    // 0 or 1: x-pixel offset
    int ch4  = lane & 15;                    // float4 chunk (16 per 64-ch half)

    const float* rp = rois + r * 5;
    int b  = (int)rp[0];
    int x1 = (int)(rp[1] * SCALE);
    int y1 = (int)(rp[2] * SCALE);
    int x2 = (int)(rp[3] * SCALE);
    int y2 = (int)(rp[4] * SCALE);
    int h = y2 - y1;
    int w = x2 - x1;
    bool empty = (h <= 0) || (w <= 0);

    const float4 NEG4 = make_float4(-CUDART_INF_F, -CUDART_INF_F,
                                    -CUDART_INF_F, -CUDART_INF_F);
    // lane-folded base: + p pixels + ch4 chunks
    const float4* bbase = reinterpret_cast<const float4*>(g_feat_t)
                        + ((size_t)b * FH * FW + p) * C4 + ch4;

    for (int bin = wid; bin < NBIN; bin += 16) {
        int ph = bin / OW;
        int pw = bin - ph * OW;

        int hs = y1 + (ph * h) / OH;
        int he = y1 + ((ph + 1) * h + OH - 1) / OH;
        int ws = x1 + (pw * w) / OW;
        int we = x1 + ((pw + 1) * w + OW - 1) / OW;

        float4 a0A = NEG4, a0B = NEG4, a1A = NEG4, a1B = NEG4;

        int y = hs;
        for (; y + 1 < he; y += 2) {
            const float4* r0 = bbase + (size_t)(y * FW) * C4;
            const float4* r1 = r0 + (size_t)FW * C4;
            #pragma unroll 2
            for (int x = ws; x < we; x += 2) {
                bool ok = (x + p) < we;
                size_t off = (size_t)x * C4;
                float4 v0A = ok ? r0[off]      : NEG4;
                float4 v0B = ok ? r0[off + 16] : NEG4;
                float4 v1A = ok ? r1[off]      : NEG4;
                float4 v1B = ok ? r1[off + 16] : NEG4;
                a0A.x = fmaxf(a0A.x, v0A.x); a0A.y = fmaxf(a0A.y, v0A.y);
                a0A.z = fmaxf(a0A.z, v0A.z); a0A.w = fmaxf(a0A.w, v0A.w);
                a0B.x = fmaxf(a0B.x, v0B.x); a0B.y = fmaxf(a0B.y, v0B.y);
                a0B.z = fmaxf(a0B.z, v0B.z); a0B.w = fmaxf(a0B.w, v0B.w);
                a1A.x = fmaxf(a1A.x, v1A.x); a1A.y = fmaxf(a1A.y, v1A.y);
                a1A.z = fmaxf(a1A.z, v1A.z); a1A.w = fmaxf(a1A.w, v1A.w);
                a1B.x = fmaxf(a1B.x, v1B.x); a1B.y = fmaxf(a1B.y, v1B.y);
                a1B.z = fmaxf(a1B.z, v1B.z); a1B.w = fmaxf(a1B.w, v1B.w);
            }
        }
        if (y < he) {                        // remainder row
            const float4* r0 = bbase + (size_t)(y * FW) * C4;
            #pragma unroll 2
            for (int x = ws; x < we; x += 2) {
                bool ok = (x + p) < we;
                size_t off = (size_t)x * C4;
                float4 v0A = ok ? r0[off]      : NEG4;
                float4 v0B = ok ? r0[off + 16] : NEG4;
                a0A.x = fmaxf(a0A.x, v0A.x); a0A.y = fmaxf(a0A.y, v0A.y);
                a0A.z = fmaxf(a0A.z, v0A.z); a0A.w = fmaxf(a0A.w, v0A.w);
                a0B.x = fmaxf(a0B.x, v0B.x); a0B.y = fmaxf(a0B.y, v0B.y);
                a0B.z = fmaxf(a0B.z, v0B.z); a0B.w = fmaxf(a0B.w, v0B.w);
            }
        }
        // merge rows
        a0A.x = fmaxf(a0A.x, a1A.x); a0A.y = fmaxf(a0A.y, a1A.y);
        a0A.z = fmaxf(a0A.z, a1A.z); a0A.w = fmaxf(a0A.w, a1A.w);
        a0B.x = fmaxf(a0B.x, a1B.x); a0B.y = fmaxf(a0B.y, a1B.y);
        a0B.z = fmaxf(a0B.z, a1B.z); a0B.w = fmaxf(a0B.w, a1B.w);

        // merge pixel-pair across lanes (lane ^ 16 has same ch4, other p)
        a0A.x = fmaxf(a0A.x, __shfl_xor_sync(0xffffffffu, a0A.x, 16));
        a0A.y = fmaxf(a0A.y, __shfl_xor_sync(0xffffffffu, a0A.y, 16));
        a0A.z = fmaxf(a0A.z, __shfl_xor_sync(0xffffffffu, a0A.z, 16));
        a0A.w = fmaxf(a0A.w, __shfl_xor_sync(0xffffffffu, a0A.w, 16));
        a0B.x = fmaxf(a0B.x, __shfl_xor_sync(0xffffffffu, a0B.x, 16));
        a0B.y = fmaxf(a0B.y, __shfl_xor_sync(0xffffffffu, a0B.y, 16));
        a0B.z = fmaxf(a0B.z, __shfl_xor_sync(0xffffffffu, a0B.z, 16));
        a0B.w = fmaxf(a0B.w, __shfl_xor_sync(0xffffffffu, a0B.w, 16));

        if (empty) {
            a0A = make_float4(0.f, 0.f, 0.f, 0.f);
            a0B = a0A;
        }

        // lanes 0-15 write channel half A (c = 4*ch4), lanes 16-31 half B
        float4 res = (p == 0) ? a0A : a0B;
        int cb = p * 64 + ch4 * 4;
        float* sp = s_out + bin;
        sp[(cb + 0) * NBIN] = res.x;
        sp[(cb + 1) * NBIN] = res.y;
        sp[(cb + 2) * NBIN] = res.z;
        sp[(cb + 3) * NBIN] = res.w;
    }
    __syncthreads();

    // Coalesced epilogue: 6272 contiguous floats = 1568 float4.
    const float4* s4 = reinterpret_cast<const float4*>(s_out);
    float4* o4 = reinterpret_cast<float4*>(out + (size_t)r * FC * NBIN);
    for (int i = threadIdx.x; i < (FC * NBIN) / 4; i += 512)
        o4[i] = s4[i];
}

extern "C" void kernel_launch(void* const* d_in, const int* in_sizes, int n_in,
                              void* d_out, int out_size) {
    const float* feat = (const float*)d_in[0];   // (2,128,64,64) fp32
    const float* rois = (const float*)d_in[1];   // (256,5) fp32
    float* out = (float*)d_out;                  // (256,128,7,7) fp32

    transpose_nchw_nhwc<<<NB * FH * 2, 256>>>(feat);
    roipool_kernel<<<NROI, 512>>>(rois, out);
}

// round 5
// speedup vs baseline: 1.4419x; 1.4419x over previous
#include <cuda_runtime.h>
#include <math_constants.h>

#define FH 64
#define FW 64
#define FC 128
#define NB 2
#define NROI 256
#define OH 7
#define OW 7
#define NBIN (OH * OW)          // 49
#define SCALE 0.0625f
#define C4 (FC / 4)             // 32 float4 per pixel

// NHWC scratch: [b][y][x][c], 4 MB (device global, no alloc)
__device__ float g_feat_t[NB * FH * FW * FC];

// ---------------------------------------------------------------------------
// Kernel 1: NCHW -> NHWC. One block per (b, y, channel-half): 256 blocks.
// Both phases coalesced, smem bank-conflict-free (65-float padded rows).
// ---------------------------------------------------------------------------
__global__ __launch_bounds__(256) void transpose_nchw_nhwc(const float* __restrict__ feat) {
    __shared__ float s[64][FW + 1];          // 64 x 65 floats = 16.6 KB
    int blk = blockIdx.x;                    // 0..255
    int choff = (blk & 1) * 64;              // channel half
    int row = blk >> 1;                      // 0..127 : b*64 + y
    int b = row >> 6;
    int y = row & 63;

    const float* src = feat + (((size_t)b * FC + choff) * FH + y) * FW;
    #pragma unroll
    for (int it = 0; it < 16; ++it) {
        int idx = threadIdx.x + it * 256;
        int c = idx >> 6;
        int x = idx & 63;
        s[c][x] = src[(size_t)c * FH * FW + x];   // coalesced 256B reads
    }
    __syncthreads();

    float* dst = g_feat_t + (size_t)row * FW * FC + choff;
    #pragma unroll
    for (int it = 0; it < 16; ++it) {
        int idx = threadIdx.x + it * 256;
        int x = idx >> 6;
        int c = idx & 63;
        dst[(size_t)x * FC + c] = s[c][x];   // coalesced 128B writes, bank-free
    }
}

// ---------------------------------------------------------------------------
// Kernel 2: one block (448 thr = 14 warps) per (roi, ph) stripe: 1792 blocks.
// Warp pair (2*pw, 2*pw+1) handles bin pw, splitting region rows even/odd.
// Lane = float4 channel chunk -> each region pixel is one coalesced 512B
// warp load. Max ~50 loads per warp -> short critical paths, fine-grained
// load balance across the chip.
// ---------------------------------------------------------------------------
__global__ __launch_bounds__(448) void roipool_kernel(const float* __restrict__ rois,
                                                      float* __restrict__ out) {
    __shared__ float4 s_acc[14][C4];         // [warp][chunk] = 7 KB

    int bx = blockIdx.x;
    int r  = bx / OH;
    int ph = bx - r * OH;
    int wid  = threadIdx.x >> 5;
    int lane = threadIdx.x & 31;

    const float* rp = rois + r * 5;
    int b  = (int)rp[0];
    int x1 = (int)(rp[1] * SCALE);
    int y1 = (int)(rp[2] * SCALE);
    int x2 = (int)(rp[3] * SCALE);
    int y2 = (int)(rp[4] * SCALE);
    int h = y2 - y1;
    int w = x2 - x1;
    bool empty = (h <= 0) || (w <= 0);

    int hs = y1 + (ph * h) / OH;
    int he = y1 + ((ph + 1) * h + OH - 1) / OH;

    {
        int pw  = wid >> 1;                  // bin column 0..6
        int par = wid & 1;                   // row parity
        int ws = x1 + (pw * w) / OW;
        int we = x1 + ((pw + 1) * w + OW - 1) / OW;

        float4 acc = make_float4(-CUDART_INF_F, -CUDART_INF_F,
                                 -CUDART_INF_F, -CUDART_INF_F);

        const float4* bbase = reinterpret_cast<const float4*>(g_feat_t)
                            + ((size_t)b * FH * FW) * C4 + lane;

        for (int y = hs + par; y < he; y += 2) {
            const float4* rowp = bbase + (size_t)(y * FW) * C4;
            #pragma unroll 4
            for (int x = ws; x < we; ++x) {
                float4 v = rowp[(size_t)x * C4];
                acc.x = fmaxf(acc.x, v.x);
                acc.y = fmaxf(acc.y, v.y);
                acc.z = fmaxf(acc.z, v.z);
                acc.w = fmaxf(acc.w, v.w);
            }
        }
        s_acc[wid][lane] = acc;              // STS.128, no conflicts
    }
    __syncthreads();

    // Epilogue: 896 outputs for this (r, ph) slice: out[r][c][ph][pw]
    const float* sf = reinterpret_cast<const float*>(s_acc);  // [14][128]
    float* obase = out + (size_t)r * FC * NBIN + ph * OW;
    #pragma unroll
    for (int it = 0; it < 2; ++it) {
        int t = threadIdx.x + it * 448;
        int c  = t / OW;
        int pw = t - c * OW;
        float v = fmaxf(sf[(2 * pw) * FC + c], sf[(2 * pw + 1) * FC + c]);
        obase[c * NBIN + pw] = empty ? 0.f : v;
    }
}

extern "C" void kernel_launch(void* const* d_in, const int* in_sizes, int n_in,
                              void* d_out, int out_size) {
    const float* feat = (const float*)d_in[0];   // (2,128,64,64) fp32
    const float* rois = (const float*)d_in[1];   // (256,5) fp32
    float* out = (float*)d_out;                  // (256,128,7,7) fp32

    transpose_nchw_nhwc<<<NB * FH * 2, 256>>>(feat);
    roipool_kernel<<<NROI * OH, 448>>>(rois, out);
}